// round 2
// baseline (speedup 1.0000x reference)
#include <cuda_runtime.h>

// ExpandHarmonics: N=2e6 rows, MAX_MULT=5 harmonics per row.
// Output buffer layout (concatenated flattened tuple, all cast to float32):
//   [0,           15N)  hkl_all        (N,5,3) int -> float
//   [15N,         20N)  wavelength_all (N,5,1)
//   [20N,         25N)  d_all          (N,5,1)
//   [25N,         30N)  refl_id        (N,5,1) int -> float (max ~7.09M < 2^24, exact)

#define HMAX_C 60
#define G_C    121
#define N_ASU_C 4
#define MAX_MULT_C 5
#define BLOCK 256

__device__ __forceinline__ int gcd2(int a, int b) {
    while (b) { int t = a % b; a = b; b = t; }
    return a;
}

__global__ __launch_bounds__(BLOCK)
void expand_harmonics_kernel(const int*   __restrict__ asu_id,
                             const int*   __restrict__ hkl,
                             const float* __restrict__ wl,
                             const float* __restrict__ dmin,
                             const float* __restrict__ Bmat,
                             const int*   __restrict__ refl,
                             float*       __restrict__ out,
                             int N)
{
    __shared__ float sB[N_ASU_C * 9];
    __shared__ float sdmin[N_ASU_C];
    __shared__ float s_hkl[BLOCK * 15];   // stride 15 (odd) -> conflict-free
    __shared__ float s_wl [BLOCK * 5];
    __shared__ float s_d  [BLOCK * 5];
    __shared__ float s_id [BLOCK * 5];

    const int t  = threadIdx.x;
    if (t < N_ASU_C * 9) sB[t] = Bmat[t];
    if (t < N_ASU_C)     sdmin[t] = dmin[t];
    __syncthreads();

    const int r0 = blockIdx.x * BLOCK;
    const int i  = r0 + t;

    if (i < N) {
        const int a = asu_id[i];
        const int h = hkl[3 * i + 0];
        const int k = hkl[3 * i + 1];
        const int l = hkl[3 * i + 2];
        const float w = wl[i];

        const bool mask = ((h | k | l) != 0);

        int n  = gcd2(gcd2(abs(h), abs(k)), abs(l));   // >= 0
        int ns = max(n, 1);
        // n divides h,k,l exactly (gcd), so trunc div == floor div here
        const int h0 = h / ns, k0 = k / ns, l0 = l / ns;

        const float wl0 = w * (float)ns;

        const float* Bm = sB + a * 9;
        const float fh = (float)h0, fk = (float)k0, fl = (float)l0;
        const float s0 = Bm[0] * fh + Bm[1] * fk + Bm[2] * fl;
        const float s1 = Bm[3] * fh + Bm[4] * fk + Bm[5] * fl;
        const float s2 = Bm[6] * fh + Bm[7] * fk + Bm[8] * fl;
        const float nrm = sqrtf(s0 * s0 + s1 * s1 + s2 * s2);
        const float d0  = 1.0f / fmaxf(nrm, 1e-6f);

        const float nmax = fminf(floorf(d0 / sdmin[a]), floorf(wl0 / 0.95f));
        const float nmin = floorf(wl0 / 1.25f) + 1.0f;

        #pragma unroll
        for (int j = 0; j < MAX_MULT_C; j++) {
            float na = nmin + (float)j;
            if (na > nmax) na = 0.0f;
            const int ni = (int)na;

            int hh = h0 * ni, kk = k0 * ni, ll = l0 * ni;
            const int ih = hh + HMAX_C, ik = kk + HMAX_C, il = ll + HMAX_C;
            const bool valid = ((unsigned)ih < G_C) & ((unsigned)ik < G_C) & ((unsigned)il < G_C);

            int rid = -1;
            if (valid) rid = __ldg(&refl[((a * G_C + ih) * G_C + ik) * G_C + il]);

            const bool absent = (rid < 0);
            float ninv;
            if (absent) { hh = 0; kk = 0; ll = 0; ninv = 0.0f; }
            else        { ninv = 1.0f / fmaxf(na, 1e-6f); }

            float dj = d0  * ninv;
            float wj = wl0 * ninv;

            if (!mask) { hh = 0; kk = 0; ll = 0; wj = 0.0f; dj = 0.0f; rid = 0; }

            s_hkl[t * 15 + 3 * j + 0] = (float)hh;
            s_hkl[t * 15 + 3 * j + 1] = (float)kk;
            s_hkl[t * 15 + 3 * j + 2] = (float)ll;
            s_wl [t * 5 + j] = wj;
            s_d  [t * 5 + j] = dj;
            s_id [t * 5 + j] = (float)rid;
        }
    }
    __syncthreads();

    // Block-cooperative coalesced copy-out
    const int nv = min(BLOCK, N - r0);
    if (nv <= 0) return;

    float* __restrict__ o0 = out + (size_t)r0 * 15;
    for (int idx = t; idx < nv * 15; idx += BLOCK) o0[idx] = s_hkl[idx];

    float* __restrict__ o1 = out + (size_t)N * 15 + (size_t)r0 * 5;
    for (int idx = t; idx < nv * 5; idx += BLOCK) o1[idx] = s_wl[idx];

    float* __restrict__ o2 = out + (size_t)N * 20 + (size_t)r0 * 5;
    for (int idx = t; idx < nv * 5; idx += BLOCK) o2[idx] = s_d[idx];

    float* __restrict__ o3 = out + (size_t)N * 25 + (size_t)r0 * 5;
    for (int idx = t; idx < nv * 5; idx += BLOCK) o3[idx] = s_id[idx];
}

extern "C" void kernel_launch(void* const* d_in, const int* in_sizes, int n_in,
                              void* d_out, int out_size)
{
    const int*   asu_id = (const int*)  d_in[0];  // (N,1) int32
    const int*   hkl    = (const int*)  d_in[1];  // (N,3) int32
    const float* wl     = (const float*)d_in[2];  // (N,1) f32
    const float* dmin   = (const float*)d_in[3];  // (4,)  f32
    const float* Bmat   = (const float*)d_in[4];  // (4,3,3) f32
    const int*   refl   = (const int*)  d_in[5];  // (4,121,121,121) int32

    const int N = in_sizes[0];
    float* out = (float*)d_out;

    const int grid = (N + BLOCK - 1) / BLOCK;
    expand_harmonics_kernel<<<grid, BLOCK>>>(asu_id, hkl, wl, dmin, Bmat, refl, out, N);
}

// round 3
// speedup vs baseline: 1.8092x; 1.8092x over previous
#include <cuda_runtime.h>

// ExpandHarmonics: N=2e6 rows, MAX_MULT=5 harmonics per row.
// Output layout (concatenated flattened tuple, float32):
//   [0,15N) hkl_all | [15N,20N) wavelength_all | [20N,25N) d_all | [25N,30N) refl_id

#define HMAX_C 60
#define G_C    121
#define MAX_MULT_C 5
#define BLOCK 256

// gcd table for a,b in [0,12]
__device__ const unsigned char GTAB[169] = {
    0,1,2,3,4,5,6,7,8,9,10,11,12,
    1,1,1,1,1,1,1,1,1,1,1,1,1,
    2,1,2,1,2,1,2,1,2,1,2,1,2,
    3,1,1,3,1,1,3,1,1,3,1,1,3,
    4,1,2,1,4,1,2,1,4,1,2,1,4,
    5,1,1,1,1,5,1,1,1,1,5,1,1,
    6,1,2,3,2,1,6,1,2,3,2,1,6,
    7,1,1,1,1,1,1,7,1,1,1,1,1,
    8,1,2,1,4,1,2,1,8,1,2,1,4,
    9,1,1,3,1,1,3,1,1,9,1,1,3,
    10,1,2,1,2,5,2,1,2,1,10,1,2,
    11,1,1,1,1,1,1,1,1,1,1,11,1,
    12,1,2,3,4,1,6,1,4,3,2,1,12
};

__global__ __launch_bounds__(BLOCK)
void expand_harmonics_kernel(const int*   __restrict__ asu_id,
                             const int*   __restrict__ hkl,
                             const float* __restrict__ wl,
                             const float* __restrict__ dmin,
                             const float* __restrict__ Bmat,
                             const int*   __restrict__ refl,
                             float*       __restrict__ out,
                             int N)
{
    __shared__ float sB[36];
    __shared__ float sdmin[4];
    __shared__ float srcp[13];
    __shared__ unsigned char sg[169];
    __shared__ __align__(16) float s_hkl[BLOCK * 15];
    __shared__ __align__(16) float s_wl [BLOCK * 5];
    __shared__ __align__(16) float s_d  [BLOCK * 5];
    __shared__ __align__(16) float s_id [BLOCK * 5];

    const int t = threadIdx.x;
    if (t < 36)  sB[t] = Bmat[t];
    if (t < 4)   sdmin[t] = dmin[t];
    if (t < 13)  srcp[t] = 1.0f / (float)max(t, 1);
    if (t < 169) sg[t] = GTAB[t];
    __syncthreads();

    const int r0 = blockIdx.x * BLOCK;
    const int i  = r0 + t;

    if (i < N) {
        const int a = asu_id[i];
        const int h = hkl[3 * i + 0];
        const int k = hkl[3 * i + 1];
        const int l = hkl[3 * i + 2];
        const float w = wl[i];

        const int ah = abs(h), ak = abs(k), al = abs(l);
        const bool mask = ((ah | ak | al) != 0);

        // gcd via shared table (|h|,|k|,|l| <= 12)
        const int g1 = sg[ah * 13 + ak];
        const int n  = sg[g1 * 13 + al];
        const int ns = max(n, 1);

        // exact division via reciprocal multiply (quotient is exact small int)
        const float rcp = srcp[ns];
        const int h0 = __float2int_rn((float)h * rcp);
        const int k0 = __float2int_rn((float)k * rcp);
        const int l0 = __float2int_rn((float)l * rcp);

        const float wl0 = w * (float)ns;

        const float* Bm = sB + a * 9;
        const float fh = (float)h0, fk = (float)k0, fl = (float)l0;
        const float s0 = Bm[0] * fh + Bm[1] * fk + Bm[2] * fl;
        const float s1 = Bm[3] * fh + Bm[4] * fk + Bm[5] * fl;
        const float s2 = Bm[6] * fh + Bm[7] * fk + Bm[8] * fl;
        const float nrm = sqrtf(s0 * s0 + s1 * s1 + s2 * s2);
        const float d0  = 1.0f / fmaxf(nrm, 1e-6f);

        const float nmax = fminf(floorf(d0 / sdmin[a]), floorf(wl0 / 0.95f));
        const float nmin = floorf(wl0 / 1.25f) + 1.0f;

        // gather addressing: addr = base0 + ni*step ; validity: ni*m <= 60
        const int step  = (h0 * G_C + k0) * G_C + l0;
        const int base0 = a * (G_C * G_C * G_C) + HMAX_C * (G_C * G_C + G_C + 1);
        const int m = max(max(abs(h0), abs(k0)), abs(l0));

        #pragma unroll
        for (int j = 0; j < MAX_MULT_C; j++) {
            float na = nmin + (float)j;
            if (na > nmax) na = 0.0f;
            const int ni = (int)na;

            int rid = -1;
            if (ni * m <= HMAX_C) rid = __ldg(&refl[base0 + ni * step]);

            const bool absent = (rid < 0);
            int hh = h0 * ni, kk = k0 * ni, ll = l0 * ni;
            float ninv;
            if (absent) { hh = 0; kk = 0; ll = 0; ninv = 0.0f; }
            else        { ninv = 1.0f / na; }   // na >= 1 here

            float dj = d0  * ninv;
            float wj = wl0 * ninv;

            if (!mask) { hh = 0; kk = 0; ll = 0; wj = 0.0f; dj = 0.0f; rid = 0; }

            s_hkl[t * 15 + 3 * j + 0] = (float)hh;
            s_hkl[t * 15 + 3 * j + 1] = (float)kk;
            s_hkl[t * 15 + 3 * j + 2] = (float)ll;
            s_wl [t * 5 + j] = wj;
            s_d  [t * 5 + j] = dj;
            s_id [t * 5 + j] = (float)rid;
        }
    }
    __syncthreads();

    // Block-cooperative coalesced copy-out (vectorized: nv is 256 or 128, both *15,*5 % 4 == 0)
    const int nv = min(BLOCK, N - r0);
    if (nv <= 0) return;

    if (((nv * 5) & 3) == 0) {
        const float4* v_hkl = (const float4*)s_hkl;
        const float4* v_wl  = (const float4*)s_wl;
        const float4* v_d   = (const float4*)s_d;
        const float4* v_id  = (const float4*)s_id;
        float4* o0 = (float4*)(out + (size_t)r0 * 15);
        float4* o1 = (float4*)(out + (size_t)N * 15 + (size_t)r0 * 5);
        float4* o2 = (float4*)(out + (size_t)N * 20 + (size_t)r0 * 5);
        float4* o3 = (float4*)(out + (size_t)N * 25 + (size_t)r0 * 5);
        const int n15 = (nv * 15) >> 2;
        const int n5  = (nv * 5)  >> 2;
        for (int idx = t; idx < n15; idx += BLOCK) o0[idx] = v_hkl[idx];
        for (int idx = t; idx < n5;  idx += BLOCK) o1[idx] = v_wl[idx];
        for (int idx = t; idx < n5;  idx += BLOCK) o2[idx] = v_d[idx];
        for (int idx = t; idx < n5;  idx += BLOCK) o3[idx] = v_id[idx];
    } else {
        float* o0 = out + (size_t)r0 * 15;
        float* o1 = out + (size_t)N * 15 + (size_t)r0 * 5;
        float* o2 = out + (size_t)N * 20 + (size_t)r0 * 5;
        float* o3 = out + (size_t)N * 25 + (size_t)r0 * 5;
        for (int idx = t; idx < nv * 15; idx += BLOCK) o0[idx] = s_hkl[idx];
        for (int idx = t; idx < nv * 5;  idx += BLOCK) o1[idx] = s_wl[idx];
        for (int idx = t; idx < nv * 5;  idx += BLOCK) o2[idx] = s_d[idx];
        for (int idx = t; idx < nv * 5;  idx += BLOCK) o3[idx] = s_id[idx];
    }
}

extern "C" void kernel_launch(void* const* d_in, const int* in_sizes, int n_in,
                              void* d_out, int out_size)
{
    const int*   asu_id = (const int*)  d_in[0];
    const int*   hkl    = (const int*)  d_in[1];
    const float* wl     = (const float*)d_in[2];
    const float* dmin   = (const float*)d_in[3];
    const float* Bmat   = (const float*)d_in[4];
    const int*   refl   = (const int*)  d_in[5];

    const int N = in_sizes[0];
    float* out = (float*)d_out;

    const int grid = (N + BLOCK - 1) / BLOCK;
    expand_harmonics_kernel<<<grid, BLOCK>>>(asu_id, hkl, wl, dmin, Bmat, refl, out, N);
}

// round 6
// speedup vs baseline: 1.8101x; 1.0005x over previous
#include <cuda_runtime.h>

// ExpandHarmonics: N=2e6 rows, MAX_MULT=5 harmonics per row.
// Output layout (concatenated flattened tuple, float32):
//   [0,15N) hkl_all | [15N,20N) wavelength_all | [20N,25N) d_all | [25N,30N) refl_id

#define HMAX_C 60
#define G_C    121
#define MAX_MULT_C 5
#define BLOCK 256

// gcd table for a,b in [0,12]
__device__ const unsigned char GTAB[169] = {
    0,1,2,3,4,5,6,7,8,9,10,11,12,
    1,1,1,1,1,1,1,1,1,1,1,1,1,
    2,1,2,1,2,1,2,1,2,1,2,1,2,
    3,1,1,3,1,1,3,1,1,3,1,1,3,
    4,1,2,1,4,1,2,1,4,1,2,1,4,
    5,1,1,1,1,5,1,1,1,1,5,1,1,
    6,1,2,3,2,1,6,1,2,3,2,1,6,
    7,1,1,1,1,1,1,7,1,1,1,1,1,
    8,1,2,1,4,1,2,1,8,1,2,1,4,
    9,1,1,3,1,1,3,1,1,9,1,1,3,
    10,1,2,1,2,5,2,1,2,1,10,1,2,
    11,1,1,1,1,1,1,1,1,1,1,11,1,
    12,1,2,3,4,1,6,1,4,3,2,1,12
};

__global__ __launch_bounds__(BLOCK, 7)
void expand_harmonics_kernel(const int*   __restrict__ asu_id,
                             const int*   __restrict__ hkl,
                             const float* __restrict__ wl,
                             const float* __restrict__ dmin,
                             const float* __restrict__ Bmat,
                             const int*   __restrict__ refl,
                             float*       __restrict__ out,
                             int N)
{
    __shared__ float sB[36];
    __shared__ float sdmin[4];
    __shared__ float srcp[32];           // 1/max(t,1), exact IEEE rcp of small ints
    __shared__ unsigned char sg[169];
    __shared__ __align__(16) float s_hkl[BLOCK * 15];
    __shared__ __align__(16) float s_wl [BLOCK * 5];
    __shared__ __align__(16) float s_d  [BLOCK * 5];
    __shared__ __align__(16) float s_id [BLOCK * 5];

    const int t = threadIdx.x;
    if (t < 36)  sB[t] = Bmat[t];
    if (t < 4)   sdmin[t] = dmin[t];
    if (t < 32)  srcp[t] = 1.0f / (float)max(t, 1);
    if (t < 169) sg[t] = GTAB[t];

    const int r0 = blockIdx.x * BLOCK;
    const int nv = min(BLOCK, N - r0);

    // ---- Stage hkl input through shared (coalesced int4 loads) ----
    int* si = (int*)s_hkl;
    if (((nv * 3) & 3) == 0) {
        const int4* gsrc = (const int4*)(hkl + (size_t)r0 * 3);
        const int cnt = (nv * 3) >> 2;
        for (int idx = t; idx < cnt; idx += BLOCK) ((int4*)si)[idx] = gsrc[idx];
    } else {
        for (int idx = t; idx < nv * 3; idx += BLOCK) si[idx] = hkl[(size_t)r0 * 3 + idx];
    }
    __syncthreads();

    const int i = r0 + t;
    int   h = 0, k = 0, l = 0;
    if (t < nv) { h = si[t * 3 + 0]; k = si[t * 3 + 1]; l = si[t * 3 + 2]; }
    __syncthreads();   // reclaim s_hkl for output staging

    if (t < nv) {
        const int a = asu_id[i];
        const float w = wl[i];

        const int ah = abs(h), ak = abs(k), al = abs(l);
        const bool mask = ((ah | ak | al) != 0);

        // gcd via shared table (|h|,|k|,|l| <= 12)
        const int g1 = sg[ah * 13 + ak];
        const int n  = sg[g1 * 13 + al];
        const int ns = max(n, 1);

        // exact division via reciprocal multiply (quotient exact small int)
        const float rcp = srcp[ns];
        const int h0 = __float2int_rn((float)h * rcp);
        const int k0 = __float2int_rn((float)k * rcp);
        const int l0 = __float2int_rn((float)l * rcp);

        const float wl0 = w * (float)ns;

        const float* Bm = sB + a * 9;
        const float fh = (float)h0, fk = (float)k0, fl = (float)l0;
        const float s0 = Bm[0] * fh + Bm[1] * fk + Bm[2] * fl;
        const float s1 = Bm[3] * fh + Bm[4] * fk + Bm[5] * fl;
        const float s2 = Bm[6] * fh + Bm[7] * fk + Bm[8] * fl;
        const float nrm = sqrtf(s0 * s0 + s1 * s1 + s2 * s2);
        const float d0  = 1.0f / fmaxf(nrm, 1e-6f);   // exact div (matches ref rounding)

        const float nmax = fminf(floorf(d0 / sdmin[a]), floorf(wl0 / 0.95f));
        const float nmin = floorf(wl0 / 1.25f) + 1.0f;

        // gather addressing: addr = base0 + ni*step ; validity: ni*m <= 60.
        // When mask==false: step==0, gather hits center which is always -1 ->
        // absent path zeroes everything; only rid needs explicit masking.
        const int step  = (h0 * G_C + k0) * G_C + l0;
        const int base0 = a * (G_C * G_C * G_C) + HMAX_C * (G_C * G_C + G_C + 1);
        const int m = max(max(abs(h0), abs(k0)), abs(l0));

        #pragma unroll
        for (int j = 0; j < MAX_MULT_C; j++) {
            float na = nmin + (float)j;
            if (na > nmax) na = 0.0f;
            const int ni = (int)na;     // 0..17

            int rid = -1;
            if (ni * m <= HMAX_C) rid = __ldg(&refl[base0 + ni * step]);

            const bool absent = (rid < 0);
            const int   ne   = absent ? 0 : ni;          // na>=1 whenever !absent
            const float ninv = absent ? 0.0f : srcp[ni]; // == 1.0f/na exactly

            const int hh = h0 * ne, kk = k0 * ne, ll = l0 * ne;
            const float dj = d0  * ninv;
            const float wj = wl0 * ninv;
            const int rid_o = mask ? rid : 0;

            s_hkl[t * 15 + 3 * j + 0] = (float)hh;
            s_hkl[t * 15 + 3 * j + 1] = (float)kk;
            s_hkl[t * 15 + 3 * j + 2] = (float)ll;
            s_wl [t * 5 + j] = wj;
            s_d  [t * 5 + j] = dj;
            s_id [t * 5 + j] = (float)rid_o;
        }
    }
    __syncthreads();

    // ---- Block-cooperative coalesced copy-out ----
    if (nv <= 0) return;

    if (((nv * 5) & 3) == 0) {
        const float4* v_hkl = (const float4*)s_hkl;
        const float4* v_wl  = (const float4*)s_wl;
        const float4* v_d   = (const float4*)s_d;
        const float4* v_id  = (const float4*)s_id;
        float4* o0 = (float4*)(out + (size_t)r0 * 15);
        float4* o1 = (float4*)(out + (size_t)N * 15 + (size_t)r0 * 5);
        float4* o2 = (float4*)(out + (size_t)N * 20 + (size_t)r0 * 5);
        float4* o3 = (float4*)(out + (size_t)N * 25 + (size_t)r0 * 5);
        const int n15 = (nv * 15) >> 2;
        const int n5  = (nv * 5)  >> 2;
        for (int idx = t; idx < n15; idx += BLOCK) o0[idx] = v_hkl[idx];
        for (int idx = t; idx < n5;  idx += BLOCK) o1[idx] = v_wl[idx];
        for (int idx = t; idx < n5;  idx += BLOCK) o2[idx] = v_d[idx];
        for (int idx = t; idx < n5;  idx += BLOCK) o3[idx] = v_id[idx];
    } else {
        float* o0 = out + (size_t)r0 * 15;
        float* o1 = out + (size_t)N * 15 + (size_t)r0 * 5;
        float* o2 = out + (size_t)N * 20 + (size_t)r0 * 5;
        float* o3 = out + (size_t)N * 25 + (size_t)r0 * 5;
        for (int idx = t; idx < nv * 15; idx += BLOCK) o0[idx] = s_hkl[idx];
        for (int idx = t; idx < nv * 5;  idx += BLOCK) o1[idx] = s_wl[idx];
        for (int idx = t; idx < nv * 5;  idx += BLOCK) o2[idx] = s_d[idx];
        for (int idx = t; idx < nv * 5;  idx += BLOCK) o3[idx] = s_id[idx];
    }
}

extern "C" void kernel_launch(void* const* d_in, const int* in_sizes, int n_in,
                              void* d_out, int out_size)
{
    const int*   asu_id = (const int*)  d_in[0];
    const int*   hkl    = (const int*)  d_in[1];
    const float* wl     = (const float*)d_in[2];
    const float* dmin   = (const float*)d_in[3];
    const float* Bmat   = (const float*)d_in[4];
    const int*   refl   = (const int*)  d_in[5];

    const int N = in_sizes[0];
    float* out = (float*)d_out;

    const int grid = (N + BLOCK - 1) / BLOCK;
    expand_harmonics_kernel<<<grid, BLOCK>>>(asu_id, hkl, wl, dmin, Bmat, refl, out, N);
}

// round 7
// speedup vs baseline: 2.2431x; 1.2392x over previous
#include <cuda_runtime.h>
#include <cstdint>

// ExpandHarmonics: N=2e6 rows, MAX_MULT=5 harmonics per row.
// Output layout (concatenated flattened tuple, float32):
//   [0,15N) hkl_all | [15N,20N) wavelength_all | [20N,25N) d_all | [25N,30N) refl_id

#define HMAX_C 60
#define G_C    121
#define MAX_MULT_C 5
#define BLOCK 256

// gcd table for a,b in [0,12]
__device__ const unsigned char GTAB[169] = {
    0,1,2,3,4,5,6,7,8,9,10,11,12,
    1,1,1,1,1,1,1,1,1,1,1,1,1,
    2,1,2,1,2,1,2,1,2,1,2,1,2,
    3,1,1,3,1,1,3,1,1,3,1,1,3,
    4,1,2,1,4,1,2,1,4,1,2,1,4,
    5,1,1,1,1,5,1,1,1,1,5,1,1,
    6,1,2,3,2,1,6,1,2,3,2,1,6,
    7,1,1,1,1,1,1,7,1,1,1,1,1,
    8,1,2,1,4,1,2,1,8,1,2,1,4,
    9,1,1,3,1,1,3,1,1,9,1,1,3,
    10,1,2,1,2,5,2,1,2,1,10,1,2,
    11,1,1,1,1,1,1,1,1,1,1,11,1,
    12,1,2,3,4,1,6,1,4,3,2,1,12
};

__device__ __forceinline__ void bulk_store_s2g(void* gdst, const void* ssrc, int bytes) {
    uint32_t s = (uint32_t)__cvta_generic_to_shared(ssrc);
    asm volatile("cp.async.bulk.global.shared::cta.bulk_group [%0], [%1], %2;"
                 :: "l"(gdst), "r"(s), "r"(bytes) : "memory");
}

__global__ __launch_bounds__(BLOCK, 7)
void expand_harmonics_kernel(const int*   __restrict__ asu_id,
                             const int*   __restrict__ hkl,
                             const float* __restrict__ wl,
                             const float* __restrict__ dmin,
                             const float* __restrict__ Bmat,
                             const int*   __restrict__ refl,
                             float*       __restrict__ out,
                             int N)
{
    __shared__ float sB[36];
    __shared__ float sdmin[4];
    __shared__ float srcp[32];           // 1/max(t,1): exact IEEE rcp of small ints
    __shared__ unsigned char sg[169];
    __shared__ __align__(16) float s_hkl[BLOCK * 15];
    __shared__ __align__(16) float s_wl [BLOCK * 5];
    __shared__ __align__(16) float s_d  [BLOCK * 5];
    __shared__ __align__(16) float s_id [BLOCK * 5];

    const int t = threadIdx.x;
    if (t < 36)  sB[t] = Bmat[t];
    if (t < 4)   sdmin[t] = dmin[t];
    if (t < 32)  srcp[t] = 1.0f / (float)max(t, 1);
    if (t < 169) sg[t] = GTAB[t];
    __syncthreads();

    const int r0 = blockIdx.x * BLOCK;
    const int nv = min(BLOCK, N - r0);
    const int i  = r0 + t;

    if (t < nv) {
        const int a = asu_id[i];
        const int h = hkl[3 * i + 0];
        const int k = hkl[3 * i + 1];
        const int l = hkl[3 * i + 2];
        const float w = wl[i];

        const int ah = abs(h), ak = abs(k), al = abs(l);
        const bool mask = ((ah | ak | al) != 0);

        // gcd via shared table (|h|,|k|,|l| <= 12)
        const int g1 = sg[ah * 13 + ak];
        const int n  = sg[g1 * 13 + al];
        const int ns = max(n, 1);

        // exact division via reciprocal multiply (quotient exact small int)
        const float rcp = srcp[ns];
        const int h0 = __float2int_rn((float)h * rcp);
        const int k0 = __float2int_rn((float)k * rcp);
        const int l0 = __float2int_rn((float)l * rcp);

        const float wl0 = w * (float)ns;

        const float* Bm = sB + a * 9;
        const float fh = (float)h0, fk = (float)k0, fl = (float)l0;
        const float s0 = Bm[0] * fh + Bm[1] * fk + Bm[2] * fl;
        const float s1 = Bm[3] * fh + Bm[4] * fk + Bm[5] * fl;
        const float s2 = Bm[6] * fh + Bm[7] * fk + Bm[8] * fl;
        const float nrm = sqrtf(s0 * s0 + s1 * s1 + s2 * s2);
        const float d0  = 1.0f / fmaxf(nrm, 1e-6f);

        const float nmax = fminf(floorf(d0 / sdmin[a]), floorf(wl0 / 0.95f));
        const float nmin = floorf(wl0 / 1.25f) + 1.0f;

        // gather addressing: addr = base0 + ni*step ; validity: ni>0 && ni*m<=60.
        // ni==0 provably yields rid=-1 (table center is always -1) -> skip the load.
        const int step  = (h0 * G_C + k0) * G_C + l0;
        const int base0 = a * (G_C * G_C * G_C) + HMAX_C * (G_C * G_C + G_C + 1);
        const int m = max(max(abs(h0), abs(k0)), abs(l0));

        #pragma unroll
        for (int j = 0; j < MAX_MULT_C; j++) {
            float na = nmin + (float)j;
            if (na > nmax) na = 0.0f;
            const int ni = (int)na;     // 0..17

            int rid = -1;
            if (ni > 0 && ni * m <= HMAX_C) rid = __ldg(&refl[base0 + ni * step]);

            const bool absent = (rid < 0);
            const int   ne   = absent ? 0 : ni;          // na>=1 whenever !absent
            const float ninv = absent ? 0.0f : srcp[ni]; // == 1.0f/na exactly

            const int hh = h0 * ne, kk = k0 * ne, ll = l0 * ne;
            const float dj = d0  * ninv;
            const float wj = wl0 * ninv;
            const int rid_o = mask ? rid : 0;

            s_hkl[t * 15 + 3 * j + 0] = (float)hh;
            s_hkl[t * 15 + 3 * j + 1] = (float)kk;
            s_hkl[t * 15 + 3 * j + 2] = (float)ll;
            s_wl [t * 5 + j] = wj;
            s_d  [t * 5 + j] = dj;
            s_id [t * 5 + j] = (float)rid_o;
        }
    }
    __syncthreads();

    // ---- Copy-out ----
    const long b15 = (long)nv * 15 * 4;   // bytes
    const long b5  = (long)nv * 5 * 4;

    const bool tma_ok = ((b15 & 15) == 0) && ((b5 & 15) == 0) &&
                        ((((long)N * 60) & 15) == 0) && (((long)r0 * 20 & 15) == 0);

    if (tma_ok) {
        if (t == 0) {
            asm volatile("fence.proxy.async.shared::cta;" ::: "memory");
            bulk_store_s2g(out + (size_t)r0 * 15,                    s_hkl, (int)b15);
            bulk_store_s2g(out + (size_t)N * 15 + (size_t)r0 * 5,    s_wl,  (int)b5);
            bulk_store_s2g(out + (size_t)N * 20 + (size_t)r0 * 5,    s_d,   (int)b5);
            bulk_store_s2g(out + (size_t)N * 25 + (size_t)r0 * 5,    s_id,  (int)b5);
            asm volatile("cp.async.bulk.commit_group;" ::: "memory");
            asm volatile("cp.async.bulk.wait_group 0;" ::: "memory");
        }
    } else {
        float* o0 = out + (size_t)r0 * 15;
        float* o1 = out + (size_t)N * 15 + (size_t)r0 * 5;
        float* o2 = out + (size_t)N * 20 + (size_t)r0 * 5;
        float* o3 = out + (size_t)N * 25 + (size_t)r0 * 5;
        for (int idx = t; idx < nv * 15; idx += BLOCK) o0[idx] = s_hkl[idx];
        for (int idx = t; idx < nv * 5;  idx += BLOCK) o1[idx] = s_wl[idx];
        for (int idx = t; idx < nv * 5;  idx += BLOCK) o2[idx] = s_d[idx];
        for (int idx = t; idx < nv * 5;  idx += BLOCK) o3[idx] = s_id[idx];
    }
}

extern "C" void kernel_launch(void* const* d_in, const int* in_sizes, int n_in,
                              void* d_out, int out_size)
{
    const int*   asu_id = (const int*)  d_in[0];
    const int*   hkl    = (const int*)  d_in[1];
    const float* wl     = (const float*)d_in[2];
    const float* dmin   = (const float*)d_in[3];
    const float* Bmat   = (const float*)d_in[4];
    const int*   refl   = (const int*)  d_in[5];

    const int N = in_sizes[0];
    float* out = (float*)d_out;

    const int grid = (N + BLOCK - 1) / BLOCK;
    expand_harmonics_kernel<<<grid, BLOCK>>>(asu_id, hkl, wl, dmin, Bmat, refl, out, N);
}